// round 13
// baseline (speedup 1.0000x reference)
#include <cuda_runtime.h>
#include <math.h>

#define NT   256
#define NS   4096
#define PIDX(i) ((i) + ((i)>>4))
// float2: A(4352)+E(4352)+tw(256)=8960*8=71680 ; floats: dbuf(8192)+red(512)+hidf(16)+pqf(64)+gam(32)=8816*4=35264
#define SMEM_BYTES 106944

// repacked weights (built by prep_kernel each launch)
__device__ float d_UV[NS*32];   // [k][r*4 + {Ur,Ui,Vr,Vi}]
__device__ float d_AC[NS*16];   // [k][r*2 + {Ar,Ai}] folded P1w combos

__global__ void prep_kernel(const float* __restrict__ Ur, const float* __restrict__ Ui,
                            const float* __restrict__ Vr, const float* __restrict__ Vi,
                            const float* __restrict__ P1w){
    int k = blockIdx.x*blockDim.x + threadIdx.x;
    if (k >= NS) return;
    int nk = (NS - k) & (NS-1);
    #pragma unroll
    for (int r=0;r<8;r++){
        d_UV[k*32 + r*4 + 0] = Ur[r*NS + k];
        d_UV[k*32 + r*4 + 1] = Ui[r*NS + k];
        d_UV[k*32 + r*4 + 2] = Vr[r*NS + k];
        d_UV[k*32 + r*4 + 3] = Vi[r*NS + k];
        float prk = P1w[r*2*NS + k],      prn = P1w[r*2*NS + nk];
        float pik = P1w[r*2*NS + NS + k], pin = P1w[r*2*NS + NS + nk];
        d_AC[k*16 + r*2 + 0] = 0.5f*(prk + prn);
        d_AC[k*16 + r*2 + 1] = 0.5f*(pik - pin);
    }
}

__device__ __forceinline__ float2 cmul(float2 a, float2 b){
    return make_float2(fmaf(a.x,b.x,-a.y*b.y), fmaf(a.x,b.y,a.y*b.x));
}
__device__ __forceinline__ float2 cadd(float2 a,float2 b){return make_float2(a.x+b.x,a.y+b.y);}
__device__ __forceinline__ float2 csub(float2 a,float2 b){return make_float2(a.x-b.x,a.y-b.y);}

__device__ __forceinline__ void dft16(float2* a){
    float2 y[16];
    #pragma unroll
    for (int b=0;b<4;b++){
        float2 x0=a[b], x1=a[4+b], x2=a[8+b], x3=a[12+b];
        float2 t0=cadd(x0,x2), t1=csub(x0,x2), t2=cadd(x1,x3), t3=csub(x1,x3);
        y[b*4+0]=cadd(t0,t2);
        y[b*4+2]=csub(t0,t2);
        y[b*4+1]=make_float2(t1.x+t3.y, t1.y-t3.x);
        y[b*4+3]=make_float2(t1.x-t3.y, t1.y+t3.x);
    }
    const float C1=0.92387953251128674f, S1=0.38268343236508978f;
    const float C2=0.70710678118654752f;
    y[5]  = cmul(y[5],  make_float2( C1,-S1));
    y[6]  = cmul(y[6],  make_float2( C2,-C2));
    y[7]  = cmul(y[7],  make_float2( S1,-C1));
    y[9]  = cmul(y[9],  make_float2( C2,-C2));
    y[10] = make_float2(y[10].y, -y[10].x);
    y[11] = cmul(y[11], make_float2(-C2,-C2));
    y[13] = cmul(y[13], make_float2( S1,-C1));
    y[14] = cmul(y[14], make_float2(-C2,-C2));
    y[15] = cmul(y[15], make_float2(-C1, S1));
    #pragma unroll
    for (int k1=0;k1<4;k1++){
        float2 x0=y[k1], x1=y[4+k1], x2=y[8+k1], x3=y[12+k1];
        float2 t0=cadd(x0,x2), t1=csub(x0,x2), t2=cadd(x1,x3), t3=csub(x1,x3);
        a[k1+0]  = cadd(t0,t2);
        a[k1+8]  = csub(t0,t2);
        a[k1+4]  = make_float2(t1.x+t3.y, t1.y-t3.x);
        a[k1+12] = make_float2(t1.x-t3.y, t1.y+t3.x);
    }
}

template<int S>
__device__ __forceinline__ void fft_stage(const float2* __restrict__ src, float2* __restrict__ dst,
                                          const float2* __restrict__ tw, int j){
    float2 a[16];
    #pragma unroll
    for (int i=0;i<16;i++) a[i]=src[PIDX(j+(i<<8))];
    {
        const int L = (S==1)?16:256;
        int m = j & (L-1);
        float2 w = tw[(S==1)?(m<<4):m];
        float2 cw = w;
        a[1]=cmul(a[1],cw);
        #pragma unroll
        for (int i=2;i<16;i++){ cw=cmul(cw,w); a[i]=cmul(a[i],cw); }
    }
    dft16(a);
    if (S==1){
        int base = (j>>4)*256 + (j&15);
        #pragma unroll
        for (int r=0;r<16;r++) dst[PIDX(base+(r<<4))] = a[r];
    } else {
        #pragma unroll
        for (int r=0;r<16;r++) dst[PIDX(j+(r<<8))] = a[r];
    }
}

__device__ __forceinline__ void fft_stage0_pack(const float* __restrict__ x0,
                                                const float* __restrict__ x1,
                                                float2* __restrict__ dst, int j){
    float2 a[16];
    #pragma unroll
    for (int i=0;i<16;i++) a[i]=make_float2(x0[j+(i<<8)], x1[j+(i<<8)]);
    dft16(a);
    int base=j<<4;
    #pragma unroll
    for (int r=0;r<16;r++) dst[PIDX(base+r)]=a[r];
}

__device__ __forceinline__ void fft_stage0_sm(const float2* __restrict__ src,
                                              float2* __restrict__ dst, int j){
    float2 a[16];
    #pragma unroll
    for (int i=0;i<16;i++) a[i]=src[PIDX(j+(i<<8))];
    dft16(a);
    int base=j<<4;
    #pragma unroll
    for (int r=0;r<16;r++) dst[PIDX(base+r)]=a[r];
}

__device__ __forceinline__ void fft_stage2_out(const float2* __restrict__ src,
                                               const float2* __restrict__ tw, int j,
                                               float* __restrict__ out0,
                                               float* __restrict__ out1, float invn){
    float2 a[16];
    #pragma unroll
    for (int i=0;i<16;i++) a[i]=src[PIDX(j+(i<<8))];
    {
        int m = j & 255;
        float2 w = tw[m];
        float2 cw = w;
        a[1]=cmul(a[1],cw);
        #pragma unroll
        for (int i=2;i<16;i++){ cw=cmul(cw,w); a[i]=cmul(a[i],cw); }
    }
    dft16(a);
    #pragma unroll
    for (int r=0;r<16;r++){
        int idx = j + (r<<8);
        int n = (NS - idx) & (NS-1);
        out0[n] = a[r].x * invn;
        out1[n] = a[r].y * invn;
    }
}

__global__ void __launch_bounds__(NT, 2)
rmix_kernel(const float* __restrict__ x,
            const float* __restrict__ Wr, const float* __restrict__ Wi,
            const float* __restrict__ P1b,
            const float* __restrict__ P2w, const float* __restrict__ P2b,
            const float* __restrict__ alphaP,
            float* __restrict__ out)
{
    extern __shared__ float2 sm[];
    float2* A  = sm;                  // 4352 : X0 / scratch
    float2* E  = sm + 4352;           // 4352 : Z / X1 / scratch
    float2* tw = sm + 8704;           // 256
    float*  fb   = (float*)(sm + 8960);
    float*  dbuf = fb;                // 2*4096
    float*  red  = fb + 8192;         // 512
    float*  hidf = fb + 8192 + 512;   // 16
    float*  pqf  = hidf + 16;         // 64
    float*  gam  = pqf + 64;          // 32

    const int tid = threadIdx.x;
    const size_t row0 = (size_t)blockIdx.x * 2;

    {
        float sn, cs;
        sincospif(-(float)tid * (1.0f/2048.0f), &sn, &cs);
        tw[tid] = make_float2(cs, sn);
    }
    __syncthreads();

    // ---- forward FFT of c = x0 + i*x1 ----
    fft_stage0_pack(x + row0*NS, x + (row0+1)*NS, E, tid); __syncthreads();
    fft_stage<1>(E, A, tw, tid); __syncthreads();
    fft_stage<2>(A, E, tw, tid); __syncthreads();   // Z in E

    // ---- hidden from packed Z + folded AC table (no unpack needed) ----
    float h[16];
    #pragma unroll
    for (int i=0;i<16;i++) h[i]=0.0f;
    for (int k = tid; k < NS; k += NT){
        float2 z = E[PIDX(k)];
        const float4* ac = (const float4*)(d_AC + k*16);
        float4 c0=ac[0], c1=ac[1], c2=ac[2], c3=ac[3];
        float av[16] = {c0.x,c0.y,c0.z,c0.w, c1.x,c1.y,c1.z,c1.w,
                        c2.x,c2.y,c2.z,c2.w, c3.x,c3.y,c3.z,c3.w};
        #pragma unroll
        for (int r=0;r<8;r++){
            float Ar = av[r*2], Ai = av[r*2+1];
            h[r]   += z.x*Ar + z.y*Ai;   // row0
            h[8+r] += z.y*Ar - z.x*Ai;   // row1
        }
    }
    {
        #pragma unroll
        for (int i=0;i<16;i++){
            float v = h[i];
            #pragma unroll
            for (int o=16;o>0;o>>=1) v += __shfl_down_sync(0xffffffffu, v, o);
            h[i]=v;
        }
        int warp = tid >> 5, lane = tid & 31;
        if (lane == 0){
            #pragma unroll
            for (int i=0;i<16;i++) red[warp*16 + i] = h[i];
        }
        __syncthreads();
        if (tid < 16){
            float s = 0.0f;
            #pragma unroll
            for (int w=0; w<NT/32; w++) s += red[w*16 + tid];
            hidf[tid] = fmaxf(s + P1b[tid & 7], 0.0f);
        }
        __syncthreads();
    }

    const float alpha = *alphaP;

    // ---- delta tables for 2 rows (float4 P2w) ----
    for (int jj = tid; jj < NS; jj += NT){
        const float4* p2 = (const float4*)(P2w + (size_t)jj*8);
        float4 w0 = p2[0], w1 = p2[1];
        float wv[8] = {w0.x,w0.y,w0.z,w0.w, w1.x,w1.y,w1.z,w1.w};
        float b = P2b[jj];
        float d0=b, d1=b;
        #pragma unroll
        for (int r=0;r<8;r++){
            d0 += hidf[r]   * wv[r];
            d1 += hidf[8+r] * wv[r];
        }
        dbuf[jj] = d0; dbuf[NS+jj] = d1;
    }
    __syncthreads();

    // ---- pair-based: unpack + gain (shared by k,nk) + joint p/q accumulation ----
    float acc[64];
    #pragma unroll
    for (int i=0;i<64;i++) acc[i]=0.0f;
    for (int k = tid; k <= NS/2; k += NT){
        int nk = (NS - k) & (NS-1);
        bool dual = (nk != k);
        // gain identical for k and nk (nf symmetric)
        float nf = (float)k * (1.0f/2048.0f);
        float t  = nf * 5.0f;
        float lb = __expf(-0.5f * t * t);
        float hd = 0.5f / (1.0f + __expf(-((nf - 0.6f) * 10.0f)));
        float bg = fmaxf(1.0f + lb - hd, 0.0f);
        float scaled = nf * 4095.0f;
        float fl = floorf(scaled);
        int lo = (int)fl;
        int up = (int)ceilf(scaled);
        float frac = scaled - fl;
        float dlo0 = dbuf[lo],    dhi0 = dbuf[up];
        float dlo1 = dbuf[NS+lo], dhi1 = dbuf[NS+up];
        float g0 = fmaxf(bg + alpha * (dlo0 + (dhi0 - dlo0)*frac), 0.0f);
        float g1 = fmaxf(bg + alpha * (dlo1 + (dhi1 - dlo1)*frac), 0.0f);
        float2 Zk = E[PIDX(k)], Zn = E[PIDX(nk)];
        float2 X0k = make_float2(0.5f*(Zk.x+Zn.x)*g0, 0.5f*(Zk.y-Zn.y)*g0);
        float2 X0n = make_float2(0.5f*(Zn.x+Zk.x)*g0, 0.5f*(Zn.y-Zk.y)*g0);
        float2 X1k = make_float2(0.5f*(Zk.y+Zn.y)*g1, 0.5f*(Zn.x-Zk.x)*g1);
        float2 X1n = make_float2(0.5f*(Zn.y+Zk.y)*g1, 0.5f*(Zk.x-Zn.x)*g1);
        A[PIDX(k)] = X0k; E[PIDX(k)] = X1k;
        if (dual){ A[PIDX(nk)] = X0n; E[PIDX(nk)] = X1n; }
        const float4* uvk = (const float4*)(d_UV + (size_t)k*32);
        #pragma unroll
        for (int r=0;r<8;r++){
            float4 w = uvk[r];             // {ur, ui, vr, vi}
            acc[r*2]      += X0k.x*w.x - X0k.y*w.y;
            acc[r*2+1]    += X0k.x*w.y + X0k.y*w.x;
            acc[16+r*2]   += X0k.x*w.z - X0k.y*w.w;
            acc[16+r*2+1] += X0k.x*w.w + X0k.y*w.z;
            acc[32+r*2]   += X1k.x*w.x - X1k.y*w.y;
            acc[32+r*2+1] += X1k.x*w.y + X1k.y*w.x;
            acc[48+r*2]   += X1k.x*w.z - X1k.y*w.w;
            acc[48+r*2+1] += X1k.x*w.w + X1k.y*w.z;
        }
        if (dual){
            const float4* uvn = (const float4*)(d_UV + (size_t)nk*32);
            #pragma unroll
            for (int r=0;r<8;r++){
                float4 w = uvn[r];
                acc[r*2]      += X0n.x*w.x - X0n.y*w.y;
                acc[r*2+1]    += X0n.x*w.y + X0n.y*w.x;
                acc[16+r*2]   += X0n.x*w.z - X0n.y*w.w;
                acc[16+r*2+1] += X0n.x*w.w + X0n.y*w.z;
                acc[32+r*2]   += X1n.x*w.x - X1n.y*w.y;
                acc[32+r*2+1] += X1n.x*w.y + X1n.y*w.x;
                acc[48+r*2]   += X1n.x*w.z - X1n.y*w.w;
                acc[48+r*2+1] += X1n.x*w.w + X1n.y*w.z;
            }
        }
    }
    {
        #pragma unroll
        for (int i=0;i<64;i++){
            float v = acc[i];
            #pragma unroll
            for (int o=16;o>0;o>>=1) v += __shfl_down_sync(0xffffffffu, v, o);
            acc[i]=v;
        }
        int warp = tid >> 5, lane = tid & 31;
        if (lane == 0){
            #pragma unroll
            for (int i=0;i<64;i++) red[warp*64 + i] = acc[i];
        }
        __syncthreads();
        if (tid < 64){
            float s = 0.0f;
            #pragma unroll
            for (int w=0; w<NT/32; w++) s += red[w*64 + tid];
            pqf[tid] = s;
        }
        __syncthreads();
    }

    // ---- gamma = p * conj(q) : pqf[row*32 + {p:0..15, q:16..31}] ----
    if (tid < 16){
        int row = tid >> 3, r = tid & 7;
        float pr = pqf[row*32 + r*2],      pi = pqf[row*32 + r*2 + 1];
        float qr = pqf[row*32 + 16 + r*2], qi = pqf[row*32 + 16 + r*2 + 1];
        gam[row*16 + r*2]     = pr*qr + pi*qi;
        gam[row*16 + r*2 + 1] = pi*qr - pr*qi;
    }
    __syncthreads();

    // ---- fused: z += gamma @ W.T  +  Hermitian combine -> w in A ----
    for (int k = tid; k <= NS/2; k += NT){
        int nk = (NS - k) & (NS-1);
        bool dual = (nk != k);
        float4 wr0 = *(const float4*)(Wr + (size_t)k*8);
        float4 wr1 = *(const float4*)(Wr + (size_t)k*8 + 4);
        float4 wi0 = *(const float4*)(Wi + (size_t)k*8);
        float4 wi1 = *(const float4*)(Wi + (size_t)k*8 + 4);
        float wrk[8] = {wr0.x,wr0.y,wr0.z,wr0.w, wr1.x,wr1.y,wr1.z,wr1.w};
        float wik[8] = {wi0.x,wi0.y,wi0.z,wi0.w, wi1.x,wi1.y,wi1.z,wi1.w};
        float wrn[8], win[8];
        if (dual){
            float4 a0 = *(const float4*)(Wr + (size_t)nk*8);
            float4 a1 = *(const float4*)(Wr + (size_t)nk*8 + 4);
            float4 b0 = *(const float4*)(Wi + (size_t)nk*8);
            float4 b1 = *(const float4*)(Wi + (size_t)nk*8 + 4);
            wrn[0]=a0.x;wrn[1]=a0.y;wrn[2]=a0.z;wrn[3]=a0.w;
            wrn[4]=a1.x;wrn[5]=a1.y;wrn[6]=a1.z;wrn[7]=a1.w;
            win[0]=b0.x;win[1]=b0.y;win[2]=b0.z;win[3]=b0.w;
            win[4]=b1.x;win[5]=b1.y;win[6]=b1.z;win[7]=b1.w;
        }
        float2 v0k = A[PIDX(k)], v0n = dual ? A[PIDX(nk)] : v0k;
        float2 v1k = E[PIDX(k)], v1n = dual ? E[PIDX(nk)] : v1k;
        #pragma unroll
        for (int r=0;r<8;r++){
            float g0r_ = gam[r*2],      g0i_ = gam[r*2+1];
            float g1r_ = gam[16+r*2],   g1i_ = gam[16+r*2+1];
            v0k.x += g0r_*wrk[r] - g0i_*wik[r];
            v0k.y += g0r_*wik[r] + g0i_*wrk[r];
            v1k.x += g1r_*wrk[r] - g1i_*wik[r];
            v1k.y += g1r_*wik[r] + g1i_*wrk[r];
            if (dual){
                v0n.x += g0r_*wrn[r] - g0i_*win[r];
                v0n.y += g0r_*win[r] + g0i_*wrn[r];
                v1n.x += g1r_*wrn[r] - g1i_*win[r];
                v1n.y += g1r_*win[r] + g1i_*wrn[r];
            }
        }
        if (!dual){ v0n = v0k; v1n = v1k; }
        float2 wk = make_float2(0.5f*(v0k.x+v0n.x) - 0.5f*(v1k.y-v1n.y),
                                0.5f*(v0k.y-v0n.y) + 0.5f*(v1k.x+v1n.x));
        float2 wn = make_float2(0.5f*(v0n.x+v0k.x) - 0.5f*(v1n.y-v1k.y),
                                0.5f*(v0n.y-v0k.y) + 0.5f*(v1n.x+v1k.x));
        A[PIDX(k)] = wk; A[PIDX(nk)] = wn;
    }
    __syncthreads();

    // ---- inverse: F = fft(w); out0[n]=Re F[-n]/N, out1[n]=Im F[-n]/N ----
    fft_stage0_sm(A, E, tid);    __syncthreads();
    fft_stage<1>(E, A, tw, tid); __syncthreads();
    const float invn = 1.0f/4096.0f;
    fft_stage2_out(A, tw, tid, out + row0*NS, out + (row0+1)*NS, invn);
}

extern "C" void kernel_launch(void* const* d_in, const int* in_sizes, int n_in,
                              void* d_out, int out_size)
{
    const float* x    = (const float*)d_in[0];
    const float* Ur   = (const float*)d_in[1];
    const float* Ui   = (const float*)d_in[2];
    const float* Vr   = (const float*)d_in[3];
    const float* Vi   = (const float*)d_in[4];
    const float* Wr   = (const float*)d_in[5];
    const float* Wi   = (const float*)d_in[6];
    const float* P1w  = (const float*)d_in[7];
    const float* P1b  = (const float*)d_in[8];
    const float* P2w  = (const float*)d_in[9];
    const float* P2b  = (const float*)d_in[10];
    const float* alph = (const float*)d_in[11];
    float* out = (float*)d_out;

    prep_kernel<<<NS/256, 256>>>(Ur, Ui, Vr, Vi, P1w);

    cudaFuncSetAttribute(rmix_kernel, cudaFuncAttributeMaxDynamicSharedMemorySize, SMEM_BYTES);
    rmix_kernel<<<1024, NT, SMEM_BYTES>>>(x, Wr, Wi, P1b, P2w, P2b, alph, out);
}